// round 7
// baseline (speedup 1.0000x reference)
#include <cuda_runtime.h>
#include <math.h>
#include <float.h>
#include <stdint.h>

#define NN 32768
#define MM 1024
#define DD 128

// ---------------- device scratch (static: no allocation allowed) ------------
static __device__ float  g_logits[(size_t)NN * MM];  // 134 MB: logits, then encodings (in place)
static __device__ float  g_x2[NN];
static __device__ float  g_e2[MM];
static __device__ float  g_prec;
static __device__ double g_ent_part[256];
static __device__ double g_sq_part[256];
static __device__ int    g_counts[MM];

// ---------------- init: precision, zero accumulators ------------------------
__global__ void k_init(const float* __restrict__ lvq) {
    int t = threadIdx.x;
    if (t == 0) g_prec = expf(-lvq[0]);
    g_ent_part[t] = 0.0;
    for (int m = t; m < MM; m += 256) g_counts[m] = 0;
}

// ---------------- row squared norms (one warp per row of 128 floats) --------
__device__ __forceinline__ void rownorm_body(const float* __restrict__ src,
                                             float* __restrict__ dst, int rows) {
    int gw   = (blockIdx.x * blockDim.x + threadIdx.x) >> 5;
    int lane = threadIdx.x & 31;
    if (gw >= rows) return;
    float4 v = reinterpret_cast<const float4*>(src + (size_t)gw * DD)[lane];
    float s = v.x * v.x + v.y * v.y + v.z * v.z + v.w * v.w;
#pragma unroll
    for (int o = 16; o > 0; o >>= 1) s += __shfl_down_sync(0xffffffffu, s, o);
    if (lane == 0) dst[gw] = s;
}
__global__ void k_x2(const float* __restrict__ X) { rownorm_body(X, g_x2, NN); }
__global__ void k_e2(const float* __restrict__ E) { rownorm_body(E, g_e2, MM); }

// ---------------- GEMM1: logits = -0.5*prec*(x2 - 2*x@e^T + e2) -------------
// 128x128 tile, BK=16, 256 threads, 8x8 micro-tile per thread (NT gemm).
__global__ void __launch_bounds__(256, 2)
k_gemm1(const float* __restrict__ X, const float* __restrict__ E) {
    __shared__ float As[16][128];
    __shared__ float Bs[16][128];
    const int rowBase = blockIdx.y * 128;
    const int colBase = blockIdx.x * 128;
    const int t  = threadIdx.x;
    const int tx = t & 15, ty = t >> 4;

    float acc[8][8];
#pragma unroll
    for (int i = 0; i < 8; i++)
#pragma unroll
        for (int j = 0; j < 8; j++) acc[i][j] = 0.f;

    for (int k0 = 0; k0 < DD; k0 += 16) {
#pragma unroll
        for (int s = 0; s < 2; s++) {
            int q = t + s * 256;
            int row = q >> 2, kq = (q & 3) << 2;
            float4 va = *reinterpret_cast<const float4*>(X + (size_t)(rowBase + row) * DD + k0 + kq);
            As[kq + 0][row] = va.x; As[kq + 1][row] = va.y;
            As[kq + 2][row] = va.z; As[kq + 3][row] = va.w;
            float4 vb = *reinterpret_cast<const float4*>(E + (size_t)(colBase + row) * DD + k0 + kq);
            Bs[kq + 0][row] = vb.x; Bs[kq + 1][row] = vb.y;
            Bs[kq + 2][row] = vb.z; Bs[kq + 3][row] = vb.w;
        }
        __syncthreads();
#pragma unroll
        for (int kk = 0; kk < 16; kk++) {
            float a[8], b[8];
            *reinterpret_cast<float4*>(&a[0]) = *reinterpret_cast<const float4*>(&As[kk][ty * 8]);
            *reinterpret_cast<float4*>(&a[4]) = *reinterpret_cast<const float4*>(&As[kk][ty * 8 + 4]);
            *reinterpret_cast<float4*>(&b[0]) = *reinterpret_cast<const float4*>(&Bs[kk][tx * 8]);
            *reinterpret_cast<float4*>(&b[4]) = *reinterpret_cast<const float4*>(&Bs[kk][tx * 8 + 4]);
#pragma unroll
            for (int i = 0; i < 8; i++)
#pragma unroll
                for (int j = 0; j < 8; j++) acc[i][j] = fmaf(a[i], b[j], acc[i][j]);
        }
        __syncthreads();
    }

    const float prec = g_prec;
    float e2r[8];
#pragma unroll
    for (int j = 0; j < 8; j++) e2r[j] = g_e2[colBase + tx * 8 + j];
#pragma unroll
    for (int i = 0; i < 8; i++) {
        int n = rowBase + ty * 8 + i;
        float xn = g_x2[n];
        float o[8];
#pragma unroll
        for (int j = 0; j < 8; j++)
            o[j] = -0.5f * prec * (xn - 2.f * acc[i][j] + e2r[j]);
        float4* dst = reinterpret_cast<float4*>(g_logits + (size_t)n * MM + colBase + tx * 8);
        dst[0] = *reinterpret_cast<float4*>(&o[0]);
        dst[1] = *reinterpret_cast<float4*>(&o[4]);
    }
}

// ---------------- block reductions (256 threads) -----------------------------
__device__ __forceinline__ float blk_sum256(float v, float* sm) {
    int t = threadIdx.x;
#pragma unroll
    for (int o = 16; o > 0; o >>= 1) v += __shfl_down_sync(0xffffffffu, v, o);
    if ((t & 31) == 0) sm[t >> 5] = v;
    __syncthreads();
    if (t == 0) {
        float s = 0.f;
#pragma unroll
        for (int w = 0; w < 8; w++) s += sm[w];
        sm[0] = s;
    }
    __syncthreads();
    float r = sm[0];
    __syncthreads();
    return r;
}
__device__ __forceinline__ float blk_max256(float v, float* sm) {
    int t = threadIdx.x;
#pragma unroll
    for (int o = 16; o > 0; o >>= 1) v = fmaxf(v, __shfl_down_sync(0xffffffffu, v, o));
    if ((t & 31) == 0) sm[t >> 5] = v;
    __syncthreads();
    if (t == 0) {
        float s = sm[0];
#pragma unroll
        for (int w = 1; w < 8; w++) s = fmaxf(s, sm[w]);
        sm[0] = s;
    }
    __syncthreads();
    float r = sm[0];
    __syncthreads();
    return r;
}
__device__ __forceinline__ double blk_sum256d(double v, double* sm) {
    int t = threadIdx.x;
#pragma unroll
    for (int o = 16; o > 0; o >>= 1) v += __shfl_down_sync(0xffffffffu, v, o);
    if ((t & 31) == 0) sm[t >> 5] = v;
    __syncthreads();
    double r = 0.0;
    if (t == 0) {
#pragma unroll
        for (int w = 0; w < 8; w++) r += sm[w];
        sm[0] = r;
    }
    __syncthreads();
    r = sm[0];
    __syncthreads();
    return r;
}

// ---------------- per-row: argmax, gumbel softmax, entropy -------------------
__global__ void __launch_bounds__(256)
k_row(const float* __restrict__ U, float* __restrict__ out_idx, int write_idx) {
    __shared__ float sf[8];
    __shared__ int   si[8];
    const int n = blockIdx.x;
    const int t = threadIdx.x;
    float* row = g_logits + (size_t)n * MM;

    float4 l4 = *reinterpret_cast<const float4*>(row + t * 4);
    float4 u4 = *reinterpret_cast<const float4*>(U + (size_t)n * MM + t * 4);
    float l[4]  = {l4.x, l4.y, l4.z, l4.w};
    float uu[4] = {u4.x, u4.y, u4.z, u4.w};

    // argmax(logits) == argmin(distances); first-occurrence tie break
    float bv = l[0]; int bi = t * 4;
#pragma unroll
    for (int c = 1; c < 4; c++)
        if (l[c] > bv) { bv = l[c]; bi = t * 4 + c; }
#pragma unroll
    for (int o = 16; o > 0; o >>= 1) {
        float ov = __shfl_down_sync(0xffffffffu, bv, o);
        int   oi = __shfl_down_sync(0xffffffffu, bi, o);
        if (ov > bv || (ov == bv && oi < bi)) { bv = ov; bi = oi; }
    }
    if ((t & 31) == 0) { sf[t >> 5] = bv; si[t >> 5] = bi; }
    __syncthreads();
    if (t == 0) {
        float m = sf[0]; int ix = si[0];
#pragma unroll
        for (int w = 1; w < 8; w++)
            if (sf[w] > m || (sf[w] == m && si[w] < ix)) { m = sf[w]; ix = si[w]; }
        sf[0] = m; si[0] = ix;
    }
    __syncthreads();
    const float gmax = sf[0];
    if (t == 0) {
        int gi = si[0];
        if (write_idx) out_idx[n] = (float)gi;
        atomicAdd(&g_counts[gi], 1);
    }
    __syncthreads();

    // gumbel-softmax encodings (tau = 1), written back in place
    const float EPSF = 1.1920929e-07f;
    float p[4];
#pragma unroll
    for (int c = 0; c < 4; c++) {
        float uc = fminf(fmaxf(uu[c], EPSF), 1.0f - EPSF);
        p[c] = l[c] - logf(-logf(uc));   // logits + gumbel
    }
    float pm = fmaxf(fmaxf(p[0], p[1]), fmaxf(p[2], p[3]));
    pm = blk_max256(pm, sf);
    float es[4]; float esum = 0.f;
#pragma unroll
    for (int c = 0; c < 4; c++) { es[c] = expf(p[c] - pm); esum += es[c]; }
    esum = blk_sum256(esum, sf);
    float inv = 1.0f / esum;
    float4 enc = make_float4(es[0] * inv, es[1] * inv, es[2] * inv, es[3] * inv);
    *reinterpret_cast<float4*>(row + t * 4) = enc;

    // sum p*logp over the row = S2/S1 - log(S1), z = l - gmax
    float s1 = 0.f, s2 = 0.f;
#pragma unroll
    for (int c = 0; c < 4; c++) {
        float z = l[c] - gmax;
        float ez = expf(z);
        s1 += ez; s2 += ez * z;
    }
    s1 = blk_sum256(s1, sf);
    s2 = blk_sum256(s2, sf);
    if (t == 0) {
        double ent = (double)s2 / (double)s1 - log((double)s1);
        atomicAdd(&g_ent_part[n & 255], ent);
    }
}

// ---------------- GEMM2: quantized = enc @ e, fused sq-error ----------------
// 128 rows x 128 cols (full D), K=1024 in BK=16 chunks (NN gemm). grid = 256.
__global__ void __launch_bounds__(256, 2)
k_gemm2(const float* __restrict__ E, const float* __restrict__ X, float* __restrict__ Q) {
    __shared__ float As[16][128];
    __shared__ float Bs[16][128];
    const int rowBase = blockIdx.x * 128;
    const int t  = threadIdx.x;
    const int tx = t & 15, ty = t >> 4;

    float acc[8][8];
#pragma unroll
    for (int i = 0; i < 8; i++)
#pragma unroll
        for (int j = 0; j < 8; j++) acc[i][j] = 0.f;

    const float* A = g_logits;  // encodings
    for (int k0 = 0; k0 < MM; k0 += 16) {
#pragma unroll
        for (int s = 0; s < 2; s++) {
            int q = t + s * 256;
            int row = q >> 2, kq = (q & 3) << 2;
            float4 va = *reinterpret_cast<const float4*>(A + (size_t)(rowBase + row) * MM + k0 + kq);
            As[kq + 0][row] = va.x; As[kq + 1][row] = va.y;
            As[kq + 2][row] = va.z; As[kq + 3][row] = va.w;
            int bk = q >> 5, bd = (q & 31) << 2;
            float4 vb = *reinterpret_cast<const float4*>(E + (size_t)(k0 + bk) * DD + bd);
            *reinterpret_cast<float4*>(&Bs[bk][bd]) = vb;
        }
        __syncthreads();
#pragma unroll
        for (int kk = 0; kk < 16; kk++) {
            float a[8], b[8];
            *reinterpret_cast<float4*>(&a[0]) = *reinterpret_cast<const float4*>(&As[kk][ty * 8]);
            *reinterpret_cast<float4*>(&a[4]) = *reinterpret_cast<const float4*>(&As[kk][ty * 8 + 4]);
            *reinterpret_cast<float4*>(&b[0]) = *reinterpret_cast<const float4*>(&Bs[kk][tx * 8]);
            *reinterpret_cast<float4*>(&b[4]) = *reinterpret_cast<const float4*>(&Bs[kk][tx * 8 + 4]);
#pragma unroll
            for (int i = 0; i < 8; i++)
#pragma unroll
                for (int j = 0; j < 8; j++) acc[i][j] = fmaf(a[i], b[j], acc[i][j]);
        }
        __syncthreads();
    }

    float sq = 0.f;
#pragma unroll
    for (int i = 0; i < 8; i++) {
        int n = rowBase + ty * 8 + i;
        const float4* xr = reinterpret_cast<const float4*>(X + (size_t)n * DD + tx * 8);
        float4 x0 = xr[0], x1 = xr[1];
        float xv[8] = {x0.x, x0.y, x0.z, x0.w, x1.x, x1.y, x1.z, x1.w};
        float o[8];
#pragma unroll
        for (int j = 0; j < 8; j++) {
            o[j] = acc[i][j];
            float d = xv[j] - o[j];
            sq = fmaf(d, d, sq);
        }
        float4* dst = reinterpret_cast<float4*>(Q + (size_t)n * DD + tx * 8);
        dst[0] = *reinterpret_cast<float4*>(&o[0]);
        dst[1] = *reinterpret_cast<float4*>(&o[4]);
    }
    __shared__ float sm[8];
    float tot = blk_sum256(sq, sm);
    if (t == 0) g_sq_part[blockIdx.x] = (double)tot;
}

// ---------------- final scalars ---------------------------------------------
__global__ void k_final(float* __restrict__ out_tail, int do_write) {
    __shared__ double sd[8];
    int t = threadIdx.x;
    double ent = g_ent_part[t];
    double sq  = g_sq_part[t];
    double pp  = 0.0;
    for (int m = t; m < MM; m += 256) {
        double a = (double)g_counts[m] * (1.0 / (double)NN);
        pp += a * log(a + 1e-10);
    }
    double entS = blk_sum256d(ent, sd);
    double sqS  = blk_sum256d(sq, sd);
    double ppS  = blk_sum256d(pp, sd);
    if (t == 0 && do_write) {
        double prec = (double)g_prec;
        out_tail[0] = (float)(0.5 * prec * sqS + entS);  // loss
        out_tail[1] = (float)exp(-ppS);                  // perplexity
    }
}

// ---------------- launch -----------------------------------------------------
extern "C" void kernel_launch(void* const* d_in, const int* in_sizes, int n_in,
                              void* d_out, int out_size) {
    const float* x  = (const float*)d_in[0];  // (N, D)
    const float* e  = (const float*)d_in[1];  // (M, D)
    const float* lv = (const float*)d_in[2];  // (1,)
    const float* u  = (const float*)d_in[3];  // (N, M)

    float* out      = (float*)d_out;
    float* out_q    = out;                                  // N*D
    float* out_idx  = out + (size_t)NN * DD;                // N
    float* out_tail = out_idx + NN;                         // loss, perplexity
    int full = (out_size >= NN * DD + NN + 2) ? 1 : 0;

    k_init<<<1, 256>>>(lv);
    k_x2<<<NN / 8, 256>>>(x);
    k_e2<<<MM / 8, 256>>>(e);
    {
        dim3 g(MM / 128, NN / 128);
        k_gemm1<<<g, 256>>>(x, e);
    }
    k_row<<<NN, 256>>>(u, out_idx, full);
    k_gemm2<<<NN / 128, 256>>>(e, x, out_q);
    k_final<<<1, 256>>>(out_tail, full);
}

// round 12
// speedup vs baseline: 1.4207x; 1.4207x over previous
#include <cuda_runtime.h>
#include <cuda_bf16.h>
#include <math.h>
#include <float.h>
#include <stdint.h>

#define NN 32768
#define MM 1024
#define DD 128

static __device__ float g_logits[(size_t)NN * MM];
static __device__ __align__(256) __nv_bfloat16 g_enc_hi[(size_t)NN * MM];
static __device__ __align__(256) __nv_bfloat16 g_enc_lo[(size_t)NN * MM];
static __device__ __align__(256) __nv_bfloat16 g_xhi[(size_t)NN * DD], g_xlo[(size_t)NN * DD];
static __device__ __align__(256) __nv_bfloat16 g_ehi[(size_t)MM * DD], g_elo[(size_t)MM * DD];
static __device__ __align__(256) __nv_bfloat16 g_eThi[(size_t)DD * MM], g_eTlo[(size_t)DD * MM];
static __device__ float  g_e2[MM];
static __device__ float  g_c1[MM];
static __device__ float  g_prec;
static __device__ double g_ent_part[256];
static __device__ double g_sq_part[256];
static __device__ int    g_counts[MM];

// ---- mma.sync helpers (sm_80+ features: safe under plain sm_103 target) ----
__device__ __forceinline__ uint32_t smem_u32(const void* p) {
    uint32_t a;
    asm("{ .reg .u64 t; cvta.to.shared.u64 t, %1; cvt.u32.u64 %0, t; }" : "=r"(a) : "l"(p));
    return a;
}
__device__ __forceinline__ void ldsm_x4(uint32_t r[4], uint32_t a) {
    asm volatile("ldmatrix.sync.aligned.m8n8.x4.shared.b16 {%0,%1,%2,%3}, [%4];"
                 : "=r"(r[0]), "=r"(r[1]), "=r"(r[2]), "=r"(r[3]) : "r"(a));
}
__device__ __forceinline__ void mma16816(float d[4], const uint32_t a[4], const uint32_t* b) {
    asm volatile(
        "mma.sync.aligned.m16n8k16.row.col.f32.bf16.bf16.f32 "
        "{%0,%1,%2,%3}, {%4,%5,%6,%7}, {%8,%9}, {%0,%1,%2,%3};"
        : "+f"(d[0]), "+f"(d[1]), "+f"(d[2]), "+f"(d[3])
        : "r"(a[0]), "r"(a[1]), "r"(a[2]), "r"(a[3]), "r"(b[0]), "r"(b[1]));
}

// ---- block reductions ----
__device__ __forceinline__ float blk_sum256(float v, float* sm) {
    int t = threadIdx.x;
#pragma unroll
    for (int o = 16; o > 0; o >>= 1) v += __shfl_down_sync(0xffffffffu, v, o);
    if ((t & 31) == 0) sm[t >> 5] = v;
    __syncthreads();
    if (t == 0) {
        float s = 0.f;
#pragma unroll
        for (int w = 0; w < 8; w++) s += sm[w];
        sm[0] = s;
    }
    __syncthreads();
    float r = sm[0];
    __syncthreads();
    return r;
}
__device__ __forceinline__ float blk_max256(float v, float* sm) {
    int t = threadIdx.x;
#pragma unroll
    for (int o = 16; o > 0; o >>= 1) v = fmaxf(v, __shfl_down_sync(0xffffffffu, v, o));
    if ((t & 31) == 0) sm[t >> 5] = v;
    __syncthreads();
    if (t == 0) {
        float s = sm[0];
#pragma unroll
        for (int w = 1; w < 8; w++) s = fmaxf(s, sm[w]);
        sm[0] = s;
    }
    __syncthreads();
    float r = sm[0];
    __syncthreads();
    return r;
}
__device__ __forceinline__ double blk_sum256d(double v, double* sm) {
    int t = threadIdx.x;
#pragma unroll
    for (int o = 16; o > 0; o >>= 1) v += __shfl_down_sync(0xffffffffu, v, o);
    if ((t & 31) == 0) sm[t >> 5] = v;
    __syncthreads();
    double r = 0.0;
    if (t == 0) {
#pragma unroll
        for (int w = 0; w < 8; w++) r += sm[w];
        sm[0] = r;
    }
    __syncthreads();
    r = sm[0];
    __syncthreads();
    return r;
}

// ---- init ----
__global__ void k_init(const float* __restrict__ lvq) {
    int t = threadIdx.x;
    if (t == 0) g_prec = expf(-lvq[0]);
    g_ent_part[t] = 0.0;
    for (int m = t; m < MM; m += 256) g_counts[m] = 0;
}

// ---- embedding prep: e2, c1, bf16 split + transpose ----
__global__ void k_prep_e(const float* __restrict__ E) {
    int gw   = (blockIdx.x * blockDim.x + threadIdx.x) >> 5;
    int lane = threadIdx.x & 31;
    if (gw >= MM) return;
    float4 v = reinterpret_cast<const float4*>(E + (size_t)gw * DD)[lane];
    float s = v.x * v.x + v.y * v.y + v.z * v.z + v.w * v.w;
#pragma unroll
    for (int o = 16; o > 0; o >>= 1) s += __shfl_down_sync(0xffffffffu, s, o);
    if (lane == 0) { g_e2[gw] = s; g_c1[gw] = -0.5f * g_prec * s; }
    float vv[4] = {v.x, v.y, v.z, v.w};
    __nv_bfloat16 h[4], l[4];
#pragma unroll
    for (int c = 0; c < 4; c++) {
        h[c] = __float2bfloat16(vv[c]);
        l[c] = __float2bfloat16(vv[c] - __bfloat162float(h[c]));
    }
    __nv_bfloat162* ph = reinterpret_cast<__nv_bfloat162*>(g_ehi + (size_t)gw * DD + lane * 4);
    __nv_bfloat162* pl = reinterpret_cast<__nv_bfloat162*>(g_elo + (size_t)gw * DD + lane * 4);
    ph[0] = __halves2bfloat162(h[0], h[1]); ph[1] = __halves2bfloat162(h[2], h[3]);
    pl[0] = __halves2bfloat162(l[0], l[1]); pl[1] = __halves2bfloat162(l[2], l[3]);
#pragma unroll
    for (int c = 0; c < 4; c++) {
        int d = lane * 4 + c;
        g_eThi[(size_t)d * MM + gw] = h[c];
        g_eTlo[(size_t)d * MM + gw] = l[c];
    }
}

// ---- x split ----
__global__ void k_x_split(const float* __restrict__ X) {
    int i = blockIdx.x * 256 + threadIdx.x;
    float4 v = reinterpret_cast<const float4*>(X)[i];
    float vv[4] = {v.x, v.y, v.z, v.w};
    __nv_bfloat16 h[4], l[4];
#pragma unroll
    for (int c = 0; c < 4; c++) {
        h[c] = __float2bfloat16(vv[c]);
        l[c] = __float2bfloat16(vv[c] - __bfloat162float(h[c]));
    }
    __nv_bfloat162* ph = reinterpret_cast<__nv_bfloat162*>(g_xhi + (size_t)i * 4);
    __nv_bfloat162* pl = reinterpret_cast<__nv_bfloat162*>(g_xlo + (size_t)i * 4);
    ph[0] = __halves2bfloat162(h[0], h[1]); ph[1] = __halves2bfloat162(h[2], h[3]);
    pl[0] = __halves2bfloat162(l[0], l[1]); pl[1] = __halves2bfloat162(l[2], l[3]);
}

// ---- GEMM1: logits' = prec*(x@e^T) + c1[col], bf16x3 via mma.sync ----
// CTA tile 128x128, warp tile 32x64 (4 warps M x 2 warps N). K=128.
// smem bf16 planes pitch 272B (136 bf16); epilogue f32 pitch 132.
#define SM1_BYTES 139264
__global__ void __launch_bounds__(256, 1) k_gemm1() {
    extern __shared__ char dsm[];
    const int t = threadIdx.x, wid = t >> 5, lane = t & 31;
    const int rowBase = blockIdx.y * 128, colBase = blockIdx.x * 128;
    const uint32_t XH = 0, XL = 34816, EH = 69632, EL = 104448;
    uint32_t sbase = smem_u32(dsm);

    const __nv_bfloat16* srcs[4] = {g_xhi, g_xlo, g_ehi, g_elo};
    const int      sb[4]   = {rowBase, rowBase, colBase, colBase};
    const uint32_t doff[4] = {XH, XL, EH, EL};
#pragma unroll
    for (int pl = 0; pl < 4; pl++)
#pragma unroll
        for (int i = 0; i < 8; i++) {
            int q = t + i * 256;
            int row = q >> 4, c = q & 15;
            uint4 v = *reinterpret_cast<const uint4*>(srcs[pl] + (size_t)(sb[pl] + row) * DD + c * 8);
            *reinterpret_cast<uint4*>(dsm + doff[pl] + row * 272 + c * 16) = v;
        }
    __syncthreads();

    const int mw = (wid & 3) * 32, nw = (wid >> 2) * 64;
    const int ar = (lane & 7) + ((lane >> 3) & 1) * 8;  // A: row within 16
    const int ac = (lane >> 4) * 8;                     // A: k within 16
    const int br = (lane & 7) + (lane >> 4) * 8;        // B: n within 16
    const int bc = ((lane >> 3) & 1) * 8;               // B: k within 16

    uint32_t aH[2], aL[2], bH[4], bL[4];
#pragma unroll
    for (int mt = 0; mt < 2; mt++) {
        aH[mt] = sbase + XH + (mw + mt * 16 + ar) * 272 + ac * 2;
        aL[mt] = sbase + XL + (mw + mt * 16 + ar) * 272 + ac * 2;
    }
#pragma unroll
    for (int p = 0; p < 4; p++) {
        bH[p] = sbase + EH + (nw + p * 16 + br) * 272 + bc * 2;
        bL[p] = sbase + EL + (nw + p * 16 + br) * 272 + bc * 2;
    }

    float acc[2][8][4];
#pragma unroll
    for (int i = 0; i < 2; i++)
#pragma unroll
        for (int j = 0; j < 8; j++)
#pragma unroll
            for (int k = 0; k < 4; k++) acc[i][j][k] = 0.f;

    for (int k0 = 0; k0 < 256; k0 += 32) {   // byte offset per k-step of 16 bf16
        uint32_t ah[2][4], al[2][4];
        ldsm_x4(ah[0], aH[0] + k0); ldsm_x4(ah[1], aH[1] + k0);
        ldsm_x4(al[0], aL[0] + k0); ldsm_x4(al[1], aL[1] + k0);
#pragma unroll
        for (int p = 0; p < 4; p++) {
            uint32_t bh[4], bl[4];
            ldsm_x4(bh, bH[p] + k0);
            ldsm_x4(bl, bL[p] + k0);
#pragma unroll
            for (int mt = 0; mt < 2; mt++) {
                mma16816(acc[mt][2 * p],     ah[mt], bh);
                mma16816(acc[mt][2 * p],     ah[mt], bl);
                mma16816(acc[mt][2 * p],     al[mt], bh);
                mma16816(acc[mt][2 * p + 1], ah[mt], bh + 2);
                mma16816(acc[mt][2 * p + 1], ah[mt], bl + 2);
                mma16816(acc[mt][2 * p + 1], al[mt], bh + 2);
            }
        }
    }
    __syncthreads();

    float* sf = reinterpret_cast<float*>(dsm);
    const int g = lane >> 2, tq = lane & 3;
#pragma unroll
    for (int mt = 0; mt < 2; mt++)
#pragma unroll
        for (int nt = 0; nt < 8; nt++) {
            int r0 = mw + mt * 16 + g, c0 = nw + nt * 8 + tq * 2;
            *reinterpret_cast<float2*>(&sf[r0 * 132 + c0])       = make_float2(acc[mt][nt][0], acc[mt][nt][1]);
            *reinterpret_cast<float2*>(&sf[(r0 + 8) * 132 + c0]) = make_float2(acc[mt][nt][2], acc[mt][nt][3]);
        }
    __syncthreads();
    const float prec = g_prec;
    int row = t >> 1, ch = (t & 1) * 64;
#pragma unroll
    for (int j = 0; j < 16; j++) {
        int col = ch + j * 4;
        float4 v  = *reinterpret_cast<float4*>(&sf[row * 132 + col]);
        float4 c1 = *reinterpret_cast<const float4*>(&g_c1[colBase + col]);
        v.x = fmaf(prec, v.x, c1.x); v.y = fmaf(prec, v.y, c1.y);
        v.z = fmaf(prec, v.z, c1.z); v.w = fmaf(prec, v.w, c1.w);
        *reinterpret_cast<float4*>(&g_logits[(size_t)(rowBase + row) * MM + colBase + col]) = v;
    }
}

// ---- per-row: argmax (+exact fp32 rescue), gumbel softmax, entropy ----
__global__ void __launch_bounds__(256)
k_row(const float* __restrict__ U, const float* __restrict__ X,
      const float* __restrict__ E, float* __restrict__ out_idx, int write_idx) {
    __shared__ float sf[8];
    __shared__ int   si[8];
    __shared__ int   s_cnt;
    __shared__ int   s_cand[16];
    const int n = blockIdx.x;
    const int t = threadIdx.x;
    const float* row = g_logits + (size_t)n * MM;

    float4 l4 = *reinterpret_cast<const float4*>(row + t * 4);
    float4 u4 = *reinterpret_cast<const float4*>(U + (size_t)n * MM + t * 4);
    float l[4]  = {l4.x, l4.y, l4.z, l4.w};
    float uu[4] = {u4.x, u4.y, u4.z, u4.w};

    float bv = l[0]; int bi = t * 4;
#pragma unroll
    for (int c = 1; c < 4; c++)
        if (l[c] > bv) { bv = l[c]; bi = t * 4 + c; }
#pragma unroll
    for (int o = 16; o > 0; o >>= 1) {
        float ov = __shfl_down_sync(0xffffffffu, bv, o);
        int   oi = __shfl_down_sync(0xffffffffu, bi, o);
        if (ov > bv || (ov == bv && oi < bi)) { bv = ov; bi = oi; }
    }
    if ((t & 31) == 0) { sf[t >> 5] = bv; si[t >> 5] = bi; }
    __syncthreads();
    if (t == 0) {
        float m = sf[0]; int ix = si[0];
#pragma unroll
        for (int w = 1; w < 8; w++)
            if (sf[w] > m || (sf[w] == m && si[w] < ix)) { m = sf[w]; ix = si[w]; }
        sf[0] = m; si[0] = ix; s_cnt = 0;
    }
    __syncthreads();
    const float gmax = sf[0];
    const int   gidx = si[0];

    const float DELTA = 1e-3f;
#pragma unroll
    for (int c = 0; c < 4; c++)
        if (l[c] >= gmax - DELTA) {
            int p = atomicAdd(&s_cnt, 1);
            if (p < 16) s_cand[p] = t * 4 + c;
        }
    __syncthreads();
    int idx = gidx;
    int cnt = s_cnt;
    if (cnt > 1 && cnt <= 16) {
        if (t < 32) {
            float4 xv = reinterpret_cast<const float4*>(X + (size_t)n * DD)[t];
            float bestv = -FLT_MAX; int besti = MM;
            for (int j = 0; j < cnt; j++) {
                int ci = s_cand[j];
                float4 ev = reinterpret_cast<const float4*>(E + (size_t)ci * DD)[t];
                float d = xv.x * ev.x + xv.y * ev.y + xv.z * ev.z + xv.w * ev.w;
#pragma unroll
                for (int o = 16; o > 0; o >>= 1) d += __shfl_down_sync(0xffffffffu, d, o);
                d = __shfl_sync(0xffffffffu, d, 0);
                float le = fmaf(g_prec, d, g_c1[ci]);
                if (le > bestv || (le == bestv && ci < besti)) { bestv = le; besti = ci; }
            }
            if (t == 0) si[1] = besti;
        }
        __syncthreads();
        idx = si[1];
    }
    if (t == 0) {
        if (write_idx) out_idx[n] = (float)idx;
        atomicAdd(&g_counts[idx], 1);
    }
    __syncthreads();

    const float EPSF = 1.1920929e-07f;
    float p[4];
#pragma unroll
    for (int c = 0; c < 4; c++) {
        float uc = fminf(fmaxf(uu[c], EPSF), 1.0f - EPSF);
        p[c] = l[c] - logf(-logf(uc));
    }
    float pm = fmaxf(fmaxf(p[0], p[1]), fmaxf(p[2], p[3]));
    pm = blk_max256(pm, sf);
    float es[4]; float esum = 0.f;
#pragma unroll
    for (int c = 0; c < 4; c++) { es[c] = expf(p[c] - pm); esum += es[c]; }
    esum = blk_sum256(esum, sf);
    float inv = 1.0f / esum;
    __nv_bfloat16 eh[4], el[4];
#pragma unroll
    for (int c = 0; c < 4; c++) {
        float ev = es[c] * inv;
        eh[c] = __float2bfloat16(ev);
        el[c] = __float2bfloat16(ev - __bfloat162float(eh[c]));
    }
    __nv_bfloat162* dh = reinterpret_cast<__nv_bfloat162*>(g_enc_hi + (size_t)n * MM + t * 4);
    __nv_bfloat162* dl = reinterpret_cast<__nv_bfloat162*>(g_enc_lo + (size_t)n * MM + t * 4);
    dh[0] = __halves2bfloat162(eh[0], eh[1]); dh[1] = __halves2bfloat162(eh[2], eh[3]);
    dl[0] = __halves2bfloat162(el[0], el[1]); dl[1] = __halves2bfloat162(el[2], el[3]);

    float s1 = 0.f, s2 = 0.f;
#pragma unroll
    for (int c = 0; c < 4; c++) {
        float z = l[c] - gmax;
        float ez = expf(z);
        s1 += ez; s2 += ez * z;
    }
    s1 = blk_sum256(s1, sf);
    s2 = blk_sum256(s2, sf);
    if (t == 0) {
        double ent = (double)s2 / (double)s1 - log((double)s1);
        atomicAdd(&g_ent_part[n & 255], ent);
    }
}

// ---- GEMM2: quantized = enc @ e (bf16x3 mma.sync), fused sq-error ----
// CTA tile 128 rows x 128 dims, K=1024 in 16 chunks of 64.
// smem bf16 planes pitch 144B (72 bf16); epilogue f32 pitch 132.
#define SM2_BYTES 73728
__global__ void __launch_bounds__(256, 2)
k_gemm2(const float* __restrict__ X, float* __restrict__ Q) {
    extern __shared__ char dsm[];
    __shared__ float sm8[8];
    const int t = threadIdx.x, wid = t >> 5, lane = t & 31;
    const int rowBase = blockIdx.x * 128;
    const uint32_t AH = 0, AL = 18432, BH = 36864, BL = 55296;
    uint32_t sbase = smem_u32(dsm);

    const int mw = (wid & 3) * 32, nw = (wid >> 2) * 64;
    const int ar = (lane & 7) + ((lane >> 3) & 1) * 8;
    const int ac = (lane >> 4) * 8;
    const int br = (lane & 7) + (lane >> 4) * 8;
    const int bc = ((lane >> 3) & 1) * 8;

    uint32_t aHb[2], aLb[2], bHb[4], bLb[4];
#pragma unroll
    for (int mt = 0; mt < 2; mt++) {
        aHb[mt] = sbase + AH + (mw + mt * 16 + ar) * 144 + ac * 2;
        aLb[mt] = sbase + AL + (mw + mt * 16 + ar) * 144 + ac * 2;
    }
#pragma unroll
    for (int p = 0; p < 4; p++) {
        bHb[p] = sbase + BH + (nw + p * 16 + br) * 144 + bc * 2;
        bLb[p] = sbase + BL + (nw + p * 16 + br) * 144 + bc * 2;
    }

    float acc[2][8][4];
#pragma unroll
    for (int i = 0; i < 2; i++)
#pragma unroll
        for (int j = 0; j < 8; j++)
#pragma unroll
            for (int k = 0; k < 4; k++) acc[i][j][k] = 0.f;

    const __nv_bfloat16* srcs[4] = {g_enc_hi, g_enc_lo, g_eThi, g_eTlo};
    const uint32_t doff[4] = {AH, AL, BH, BL};

    for (int chunk = 0; chunk < 16; chunk++) {
        int k0 = chunk * 64;
        __syncthreads();
#pragma unroll
        for (int pl = 0; pl < 4; pl++) {
            int base_row = (pl < 2) ? rowBase : 0;
#pragma unroll
            for (int i = 0; i < 4; i++) {
                int q = t + i * 256;
                int row = q >> 3, c = q & 7;
                uint4 v = *reinterpret_cast<const uint4*>(
                    srcs[pl] + (size_t)(base_row + row) * MM + k0 + c * 8);
                *reinterpret_cast<uint4*>(dsm + doff[pl] + row * 144 + c * 16) = v;
            }
        }
        __syncthreads();
#pragma unroll
        for (int kk = 0; kk < 128; kk += 32) {   // byte offsets: 4 ksteps of 16 bf16
            uint32_t ah[2][4], al[2][4];
            ldsm_x4(ah[0], aHb[0] + kk); ldsm_x4(ah[1], aHb[1] + kk);
            ldsm_x4(al[0], aLb[0] + kk); ldsm_x4(al[1], aLb[1] + kk);
#pragma unroll
            for (int p = 0; p < 4; p++) {
                uint32_t bh[4], bl[4];
                ldsm_x4(bh, bHb[p] + kk);
                ldsm_x4(bl, bLb[p] + kk);
#pragma unroll
                for (int mt = 0; mt < 2; mt++) {
                    mma16816(acc[mt][2 * p],     ah[mt], bh);
                    mma16816(acc[mt][2 * p],     ah[mt], bl);
                    mma16816(acc[mt][2 * p],     al[mt], bh);
                    mma16816(acc[mt][2 * p + 1], ah[mt], bh + 2);
                    mma16816(acc[mt][2 * p + 1], ah[mt], bl + 2);
                    mma16816(acc[mt][2 * p + 1], al[mt], bh + 2);
                }
            }
        }
    }
    __syncthreads();

    float* sf = reinterpret_cast<float*>(dsm);
    const int g = lane >> 2, tq = lane & 3;
#pragma unroll
    for (int mt = 0; mt < 2; mt++)
#pragma unroll
        for (int nt = 0; nt < 8; nt++) {
            int r0 = mw + mt * 16 + g, c0 = nw + nt * 8 + tq * 2;
            *reinterpret_cast<float2*>(&sf[r0 * 132 + c0])       = make_float2(acc[mt][nt][0], acc[mt][nt][1]);
            *reinterpret_cast<float2*>(&sf[(r0 + 8) * 132 + c0]) = make_float2(acc[mt][nt][2], acc[mt][nt][3]);
        }
    __syncthreads();
    float sq = 0.f;
    int row = t >> 1, ch = (t & 1) * 64;
#pragma unroll
    for (int j = 0; j < 16; j++) {
        int col = ch + j * 4;
        float4 qv = *reinterpret_cast<float4*>(&sf[row * 132 + col]);
        float4 xv = *reinterpret_cast<const float4*>(&X[(size_t)(rowBase + row) * DD + col]);
        float dx = xv.x - qv.x, dy = xv.y - qv.y, dz = xv.z - qv.z, dw = xv.w - qv.w;
        sq += dx * dx + dy * dy + dz * dz + dw * dw;
        *reinterpret_cast<float4*>(&Q[(size_t)(rowBase + row) * DD + col]) = qv;
    }
    float tot = blk_sum256(sq, sm8);
    if (t == 0) g_sq_part[blockIdx.x] = (double)tot;
}

// ---- final scalars ----
__global__ void k_final(float* __restrict__ out_tail, int do_write) {
    __shared__ double sd[8];
    int t = threadIdx.x;
    double ent = g_ent_part[t];
    double sq  = g_sq_part[t];
    double pp  = 0.0;
    for (int m = t; m < MM; m += 256) {
        double a = (double)g_counts[m] * (1.0 / (double)NN);
        pp += a * log(a + 1e-10);
    }
    double entS = blk_sum256d(ent, sd);
    double sqS  = blk_sum256d(sq, sd);
    double ppS  = blk_sum256d(pp, sd);
    if (t == 0 && do_write) {
        double prec = (double)g_prec;
        out_tail[0] = (float)(0.5 * prec * sqS + entS);
        out_tail[1] = (float)exp(-ppS);
    }
}

// ---- launch ----
extern "C" void kernel_launch(void* const* d_in, const int* in_sizes, int n_in,
                              void* d_out, int out_size) {
    const float* x  = (const float*)d_in[0];
    const float* e  = (const float*)d_in[1];
    const float* lv = (const float*)d_in[2];
    const float* u  = (const float*)d_in[3];

    float* out      = (float*)d_out;
    float* out_q    = out;
    float* out_idx  = out + (size_t)NN * DD;
    float* out_tail = out_idx + NN;
    int full = (out_size >= NN * DD + NN + 2) ? 1 : 0;

    cudaFuncSetAttribute(k_gemm1, cudaFuncAttributeMaxDynamicSharedMemorySize, SM1_BYTES);
    cudaFuncSetAttribute(k_gemm2, cudaFuncAttributeMaxDynamicSharedMemorySize, SM2_BYTES);

    k_init<<<1, 256>>>(lv);
    k_prep_e<<<MM / 8, 256>>>(e);
    k_x_split<<<(NN * DD / 4) / 256, 256>>>(x);
    {
        dim3 g(MM / 128, NN / 128);
        k_gemm1<<<g, 256, SM1_BYTES>>>();
    }
    k_row<<<NN, 256>>>(u, x, e, out_idx, full);
    k_gemm2<<<NN / 128, 256, SM2_BYTES>>>(x, out_q);
    k_final<<<1, 256>>>(out_tail, full);
}